// round 13
// baseline (speedup 1.0000x reference)
#include <cuda_runtime.h>

// ---------------- problem constants ----------------
#define Bq   8
#define Np   16384
#define Sq   2048
#define Kq   32
#define CIN  64
#define C0   67      // 3 + CIN
#define C3   128
#define PTOT (Bq*Sq*Kq)   // 524288
#define EPSV 1e-5f

// ---------------- device scratch ----------------
struct __align__(16) FSlot {
    float x, y, z; unsigned int pad0;
    unsigned long long packed;
    unsigned long long pad1;
};
__device__ FSlot g_slot[Bq][16];
__device__ int   g_fps_idx[Bq*Sq];
__device__ int   g_knn_idx[PTOT];
__device__ float g_pointsT[(long)Bq*Np*CIN];
__device__ float g_feats[(long)PTOT*C0];
__device__ float g_x0[(long)PTOT*64];
__device__ float g_x1[(long)PTOT*64];
__device__ float g_mx[(long)Bq*Sq*C3];
__device__ float g_mn[(long)Bq*Sq*C3];
__device__ float g_stats[256];
__device__ float g_scale[128];
__device__ float g_shift[128];

__device__ __forceinline__ void st_release_u64(unsigned long long* p, unsigned long long v) {
    asm volatile("st.global.release.gpu.u64 [%0], %1;" :: "l"(p), "l"(v) : "memory");
}
__device__ __forceinline__ unsigned long long ld_acquire_u64(const unsigned long long* p) {
    unsigned long long v;
    asm volatile("ld.global.acquire.gpu.u64 %0, [%1];" : "=l"(v) : "l"(p) : "memory");
    return v;
}

// ---------------- init ----------------
__global__ void k_zero() {
    int t = threadIdx.x;
    if (t < 256) g_stats[t] = 0.f;
    if (t < Bq*16) g_slot[t >> 4][t & 15].packed = 0ull;
}
__global__ void k_zstats() {
    g_stats[threadIdx.x] = 0.f;
}

// ---------------- FPS: 16 CTAs/batch, tagged-slot release/acquire sync ----------------
__global__ void __launch_bounds__(256) k_fps(const float* __restrict__ xyz,
                                             float* __restrict__ out) {
    int j   = blockIdx.x;          // 0..15 within batch
    int b   = blockIdx.y;
    int tid = threadIdx.x;
    const float* xb = xyz + b*3*Np;
    int base = j * 1024;

    float px[4], py[4], pz[4], dist[4];
#pragma unroll
    for (int i = 0; i < 4; i++) {
        int n = base + i*256 + tid;
        px[i] = xb[n]; py[i] = xb[Np + n]; pz[i] = xb[2*Np + n];
        dist[i] = 1e10f;
    }

    __shared__ unsigned long long s_w[8];
    __shared__ float s_wx[8], s_wy[8], s_wz[8];
    __shared__ float s_cx, s_cy, s_cz;
    __shared__ int   s_ci;

    int   cur = 0;
    float cx = xb[0], cy = xb[Np], cz = xb[2*Np];
    FSlot* slots = &g_slot[b][0];
    int wid = tid >> 5, lane = tid & 31;

    for (int s = 0; s < Sq; s++) {
        if (j == 0 && tid == 0) {
            g_fps_idx[b*Sq + s] = cur;
            out[b*3*Sq + s]        = cx;
            out[b*3*Sq + Sq + s]   = cy;
            out[b*3*Sq + 2*Sq + s] = cz;
        }
        if (s == Sq - 1) break;

        // ---- distance update + local argmax (max dist, min idx on ties) ----
        unsigned long long best = 0ull;
        float bx = 0.f, by = 0.f, bz = 0.f;
#pragma unroll
        for (int i = 0; i < 4; i++) {
            float dx = px[i] - cx, dy = py[i] - cy, dz = pz[i] - cz;
            float d  = dx*dx + dy*dy + dz*dz;
            float nd = fminf(dist[i], d);
            dist[i] = nd;
            int n = base + i*256 + tid;
            unsigned long long pk =
                ((unsigned long long)__float_as_uint(nd) << 32) |
                ((unsigned long long)(unsigned)(16383 - n) << 12);
            if (pk > best) { best = pk; bx = px[i]; by = py[i]; bz = pz[i]; }
        }
        // warp reduce (carry coords)
#pragma unroll
        for (int o = 16; o; o >>= 1) {
            unsigned long long opk = __shfl_down_sync(0xffffffffu, best, o);
            float ox = __shfl_down_sync(0xffffffffu, bx, o);
            float oy = __shfl_down_sync(0xffffffffu, by, o);
            float oz = __shfl_down_sync(0xffffffffu, bz, o);
            if (opk > best) { best = opk; bx = ox; by = oy; bz = oz; }
        }
        if (lane == 0) { s_w[wid] = best; s_wx[wid] = bx; s_wy[wid] = by; s_wz[wid] = bz; }
        __syncthreads();

        if (wid == 0) {
            unsigned int tag = (unsigned)(s + 1) & 0xFFFu;
            best = (lane < 8) ? s_w[lane] : 0ull;
            bx = (lane < 8) ? s_wx[lane] : 0.f;
            by = (lane < 8) ? s_wy[lane] : 0.f;
            bz = (lane < 8) ? s_wz[lane] : 0.f;
#pragma unroll
            for (int o = 4; o; o >>= 1) {
                unsigned long long opk = __shfl_down_sync(0xffffffffu, best, o);
                float ox = __shfl_down_sync(0xffffffffu, bx, o);
                float oy = __shfl_down_sync(0xffffffffu, by, o);
                float oz = __shfl_down_sync(0xffffffffu, bz, o);
                if (opk > best) { best = opk; bx = ox; by = oy; bz = oz; }
            }
            if (lane == 0) {
                float4 c4 = make_float4(bx, by, bz, 0.f);
                *(float4*)&slots[j].x = c4;               // coords first
                st_release_u64(&slots[j].packed, best | tag);  // release: publish
            }
            // poll all 16 slots (lanes 0-15)
            bool mine = lane < 16;
            unsigned long long* pp = &slots[mine ? lane : 0].packed;
            unsigned long long v = 0ull;
            for (;;) {
                v = ld_acquire_u64(pp);
                bool ok = !mine || (((unsigned)v & 0xFFFu) == tag);
                if (__ballot_sync(0xffffffffu, ok) == 0xffffffffu) break;
            }
            // prefetch coords (overlaps reduce below)
            float sx = 0.f, sy = 0.f, sz = 0.f;
            if (mine) { sx = slots[lane].x; sy = slots[lane].y; sz = slots[lane].z; }
            unsigned long long val = mine ? (v & ~0xFFFull) : 0ull;
#pragma unroll
            for (int o = 8; o; o >>= 1)
                val = max(val, __shfl_xor_sync(0xffffffffu, val, o));
            int n  = 16383 - (int)((unsigned)(val >> 12) & 0x3FFFu);
            int jw = n >> 10;
            float cxn = __shfl_sync(0xffffffffu, sx, jw);
            float cyn = __shfl_sync(0xffffffffu, sy, jw);
            float czn = __shfl_sync(0xffffffffu, sz, jw);
            if (lane == 0) { s_ci = n; s_cx = cxn; s_cy = cyn; s_cz = czn; }
        }
        __syncthreads();
        cur = s_ci; cx = s_cx; cy = s_cy; cz = s_cz;
    }
}

// ---------------- kNN: branchless register top-K insertion ----------------
__global__ void __launch_bounds__(128) k_knn(const float* __restrict__ xyz) {
    int b = blockIdx.y;
    int s = blockIdx.x * 128 + threadIdx.x;
    const float* xb = xyz + b*3*Np;
    int qn = g_fps_idx[b*Sq + s];
    float qx = xb[qn], qy = xb[Np + qn], qz = xb[2*Np + qn];
    float q2 = qx*qx + qy*qy + qz*qz;

    float bd[Kq]; int bi[Kq];
#pragma unroll
    for (int k = 0; k < Kq; k++) { bd[k] = 3.0e38f; bi[k] = 0; }

    __shared__ float4 sp[512];
    for (int n0 = 0; n0 < Np; n0 += 512) {
        __syncthreads();
        for (int t = threadIdx.x; t < 512; t += 128) {
            float x = xb[n0 + t], y = xb[Np + n0 + t], z = xb[2*Np + n0 + t];
            sp[t] = make_float4(x, y, z, x*x + y*y + z*z);
        }
        __syncthreads();
#pragma unroll 2
        for (int t = 0; t < 512; t++) {
            float4 p = sp[t];
            float d = (q2 + p.w) - 2.0f * (qx*p.x + qy*p.y + qz*p.z);
            if (d < bd[Kq-1]) {
                int ii = n0 + t;
                // branchless unrolled shift-insert, all indices static -> registers
#pragma unroll
                for (int k = Kq - 1; k > 0; k--) {
                    bool ck   = d < bd[k];
                    bool ckm1 = d < bd[k-1];
                    float nv = ckm1 ? bd[k-1] : d;
                    int   ni = ckm1 ? bi[k-1] : ii;
                    bd[k] = ck ? nv : bd[k];
                    bi[k] = ck ? ni : bi[k];
                }
                bool c0 = d < bd[0];
                bd[0] = c0 ? d : bd[0];
                bi[0] = c0 ? ii : bi[0];
            }
        }
    }
    int o = (b*Sq + s) * Kq;
#pragma unroll
    for (int k = 0; k < Kq; k++) g_knn_idx[o + k] = bi[k];
}

// ---------------- transpose points (B,C,N) -> (B,N,C) ----------------
__global__ void k_transpose(const float* __restrict__ pts) {
    __shared__ float tile[32][33];
    int b  = blockIdx.z;
    int n0 = blockIdx.x * 32, c0 = blockIdx.y * 32;
    int x = threadIdx.x, y = threadIdx.y;
    for (int r = y; r < 32; r += 8)
        tile[r][x] = pts[(long)b*CIN*Np + (c0 + r)*Np + n0 + x];
    __syncthreads();
    for (int r = y; r < 32; r += 8)
        g_pointsT[((long)b*Np + (n0 + r)) * CIN + c0 + x] = tile[x][r];
}

// ---------------- gather + concat -> feats [p][67] ----------------
__global__ void k_gather(const float* __restrict__ xyz) {
    long t = (long)blockIdx.x * blockDim.x + threadIdx.x;
    if (t >= (long)PTOT * C0) return;
    int p = (int)(t / C0);
    int i = (int)(t - (long)p * C0);
    int b = p >> 16;
    int s = (p >> 5) & (Sq - 1);
    int n = g_knn_idx[p];
    float v;
    if (i < 3) {
        const float* xb = xyz + b*3*Np;
        int q = g_fps_idx[b*Sq + s];
        v = xb[i*Np + n] - xb[i*Np + q];
    } else {
        v = g_pointsT[((long)b*Np + n) * CIN + (i - 3)];
    }
    g_feats[t] = v;
}

// ---------------- conv GEMM + fused BN-of-prev + fused stats (+max/min for L2) ----
template<int LAYER>
__global__ void __launch_bounds__(256) k_conv(const float* __restrict__ W) {
    constexpr int CI = (LAYER == 0) ? 67 : 64;
    constexpr int CO = (LAYER == 2) ? 128 : 64;
    constexpr bool BN = (LAYER != 0);
    constexpr int TN = CO / 16;
    const float* A = (LAYER == 0) ? g_feats : ((LAYER == 1) ? g_x0 : g_x1);
    float*       O = (LAYER == 0) ? g_x0 : g_x1;

    __shared__ __align__(16) float sA[16][68];
    __shared__ __align__(16) float sBt[16][CO + 4];
    __shared__ float sS[64], sH[64];
    __shared__ float sSum[16][CO], sSq[16][CO];
    __shared__ float sMx[(LAYER == 2) ? 16 : 1][(LAYER == 2) ? CO : 1];
    __shared__ float sMn[(LAYER == 2) ? 16 : 1][(LAYER == 2) ? CO : 1];

    int tid = threadIdx.x;
    int m0  = blockIdx.x * 64;
    int tx = tid & 15, ty = tid >> 4;

    if (BN && tid < CI) { sS[tid] = g_scale[tid]; sH[tid] = g_shift[tid]; }

    float acc[4][TN];
#pragma unroll
    for (int i = 0; i < 4; i++)
#pragma unroll
        for (int jj = 0; jj < TN; jj++) acc[i][jj] = 0.f;

    const int KCH = (CI + 15) / 16;
    for (int kc = 0; kc < KCH; kc++) {
        int k0 = kc * 16;
        __syncthreads();
#pragma unroll
        for (int r = 0; r < 4; r++) {
            int e = tid + 256 * r;
            int m = e >> 4, kk = e & 15;
            int col = k0 + kk;
            float v = 0.f;
            if (col < CI) {
                v = A[(m0 + m) * CI + col];
                if (BN) v = fmaxf(v * sS[col] + sH[col], 0.f);
            }
            sA[kk][m] = v;
        }
#pragma unroll
        for (int r = 0; r < (CO * 16) / 256; r++) {
            int e = tid + 256 * r;
            int co = e >> 4, kk = e & 15;
            int col = k0 + kk;
            sBt[kk][co] = (col < CI) ? W[co * CI + col] : 0.f;
        }
        __syncthreads();
#pragma unroll
        for (int kk = 0; kk < 16; kk++) {
            float4 a4 = *(const float4*)&sA[kk][ty * 4];
            float a[4] = {a4.x, a4.y, a4.z, a4.w};
            float bb[TN];
#pragma unroll
            for (int q = 0; q < TN; q += 4) {
                float4 b4 = *(const float4*)&sBt[kk][tx * TN + q];
                bb[q] = b4.x; bb[q+1] = b4.y; bb[q+2] = b4.z; bb[q+3] = b4.w;
            }
#pragma unroll
            for (int i = 0; i < 4; i++)
#pragma unroll
                for (int jj = 0; jj < TN; jj++)
                    acc[i][jj] += a[i] * bb[jj];
        }
    }

    // output (layers 0/1 only; layer 2 output is consumed by the epilogue)
    if (LAYER < 2) {
#pragma unroll
        for (int i = 0; i < 4; i++) {
            int row = m0 + ty * 4 + i;
#pragma unroll
            for (int jj = 0; jj < TN; jj += 4) {
                float4 v = make_float4(acc[i][jj], acc[i][jj+1], acc[i][jj+2], acc[i][jj+3]);
                *(float4*)&O[row * CO + tx * TN + jj] = v;
            }
        }
    }

    // ---- fused epilogue: per-channel sum/sumsq (+ per-(b,s) max/min for L2) ----
#pragma unroll
    for (int jj = 0; jj < TN; jj++) {
        float cs = 0.f, cq = 0.f;
        float mx = -3.0e38f, mn = 3.0e38f;
#pragma unroll
        for (int i = 0; i < 4; i++) {
            float v = acc[i][jj];
            cs += v; cq = fmaf(v, v, cq);
            mx = fmaxf(mx, v); mn = fminf(mn, v);
        }
        int col = tx * TN + jj;
        sSum[ty][col] = cs;
        sSq[ty][col]  = cq;
        if (LAYER == 2) { sMx[ty][col] = mx; sMn[ty][col] = mn; }
    }
    __syncthreads();
    if (tid < CO) {
        float s = 0.f, q = 0.f;
#pragma unroll
        for (int r = 0; r < 16; r++) { s += sSum[r][tid]; q += sSq[r][tid]; }
        atomicAdd(&g_stats[tid], s);
        atomicAdd(&g_stats[128 + tid], q);
    }
    if (LAYER == 2) {
        int h = tid >> 7, c = tid & 127;
        float mx = -3.0e38f, mn = 3.0e38f;
#pragma unroll
        for (int r = 0; r < 8; r++) {
            mx = fmaxf(mx, sMx[h*8 + r][c]);
            mn = fminf(mn, sMn[h*8 + r][c]);
        }
        int bs = (m0 >> 5) + h;     // 64 rows = 2 (b,s) groups of Kq=32
        g_mx[(long)bs * C3 + c] = mx;
        g_mn[(long)bs * C3 + c] = mn;
    }
}

// ---------------- BN finalize ----------------
__global__ void k_bnfin(const float* __restrict__ g, const float* __restrict__ bb, int CO) {
    int c = threadIdx.x;
    if (c < CO) {
        const float inv = 1.0f / (float)PTOT;
        float mean = g_stats[c] * inv;
        float var  = fmaxf(g_stats[128 + c] * inv - mean * mean, 0.f);
        float sc   = g[c] / sqrtf(var + EPSV);
        g_scale[c] = sc;
        g_shift[c] = bb[c] - mean * sc;
    }
}

// ---------------- final: BN2+ReLU+maxpool from (mx,mn), transposed store ------
__global__ void __launch_bounds__(256) k_final(float* __restrict__ out) {
    __shared__ float sOut[128][33];
    int b  = blockIdx.y;
    int s0 = blockIdx.x * 32;
    int t  = threadIdx.x;
#pragma unroll
    for (int i = 0; i < 16; i++) {
        int idx = i * 256 + t;
        int c = idx & 127, r = idx >> 7;
        long bs = (long)(b * Sq + s0 + r);
        float sc = g_scale[c], sh = g_shift[c];
        float v = (sc >= 0.f) ? g_mx[bs * C3 + c] : g_mn[bs * C3 + c];
        sOut[c][r] = fmaxf(v * sc + sh, 0.f);
    }
    __syncthreads();
#pragma unroll
    for (int i = 0; i < 16; i++) {
        int idx = i * 256 + t;
        int c = idx >> 5, r = idx & 31;
        out[Bq*3*Sq + b*C3*Sq + c*Sq + s0 + r] = sOut[c][r];
    }
}

// ---------------- launch ----------------
extern "C" void kernel_launch(void* const* d_in, const int* in_sizes, int n_in,
                              void* d_out, int out_size) {
    const float* xyz    = (const float*)d_in[0];
    const float* points = (const float*)d_in[1];
    const float* W0 = (const float*)d_in[2];
    const float* g0 = (const float*)d_in[3];
    const float* b0 = (const float*)d_in[4];
    const float* W1 = (const float*)d_in[5];
    const float* g1 = (const float*)d_in[6];
    const float* b1 = (const float*)d_in[7];
    const float* W2 = (const float*)d_in[8];
    const float* g2 = (const float*)d_in[9];
    const float* b2 = (const float*)d_in[10];
    float* out = (float*)d_out;

    k_zero<<<1, 256>>>();
    k_fps<<<dim3(16, Bq), 256>>>(xyz, out);
    k_knn<<<dim3(Sq/128, Bq), 128>>>(xyz);
    k_transpose<<<dim3(Np/32, CIN/32, Bq), dim3(32, 8)>>>(points);
    {
        long tot = (long)PTOT * C0;
        k_gather<<<(unsigned)((tot + 255) / 256), 256>>>(xyz);
    }
    k_conv<0><<<PTOT/64, 256>>>(W0);
    k_bnfin<<<1, 128>>>(g0, b0, 64);
    k_zstats<<<1, 256>>>();

    k_conv<1><<<PTOT/64, 256>>>(W1);
    k_bnfin<<<1, 128>>>(g1, b1, 64);
    k_zstats<<<1, 256>>>();

    k_conv<2><<<PTOT/64, 256>>>(W2);
    k_bnfin<<<1, 128>>>(g2, b2, 128);

    k_final<<<dim3(Sq/32, Bq), 256>>>(out);
}

// round 16
// speedup vs baseline: 1.5048x; 1.5048x over previous
#include <cuda_runtime.h>

// ---------------- problem constants ----------------
#define Bq   8
#define Np   16384
#define Sq   2048
#define Kq   32
#define CIN  64
#define C0   67      // 3 + CIN
#define C3   128
#define PTOT (Bq*Sq*Kq)   // 524288
#define EPSV 1e-5f

// ---------------- device scratch ----------------
__device__ int   g_fps_idx[Bq*Sq];
__device__ int   g_knn_idx[PTOT];
__device__ float g_pointsT[(long)Bq*Np*CIN];
__device__ float g_feats[(long)PTOT*C0];
__device__ float g_x0[(long)PTOT*64];
__device__ float g_x1[(long)PTOT*64];
__device__ float g_mx[(long)Bq*Sq*C3];
__device__ float g_mn[(long)Bq*Sq*C3];
__device__ float g_stats[256];
__device__ float g_scale[128];
__device__ float g_shift[128];
__device__ unsigned int       g_cnt[Bq];
__device__ unsigned long long g_part[Bq][2][16];

// ---------------- init ----------------
__global__ void k_zero() {
    int t = threadIdx.x;
    if (t < 256) g_stats[t] = 0.f;
    if (t < Bq)  g_cnt[t] = 0u;
}
__global__ void k_zstats() { g_stats[threadIdx.x] = 0.f; }

// ---------------- FPS: 16 CTAs per batch, counter-spin sync ------------------
// VERBATIM from the R12 passing kernel (rel_err 9.6e-7 => argmax-exact).
// The distance arithmetic below is rounding-locked against the reference; do
// not restructure this loop (contraction choice is context-dependent).
__device__ __forceinline__ unsigned long long pk_max(unsigned long long a, unsigned long long b) {
    return a > b ? a : b;
}

__global__ void __launch_bounds__(256) k_fps(const float* __restrict__ xyz,
                                             float* __restrict__ out) {
    int j   = blockIdx.x;          // block within batch: 0..15
    int b   = blockIdx.y;
    int tid = threadIdx.x;
    const float* xb = xyz + b*3*Np;
    int base = j * 1024;

    float px[4], py[4], pz[4], dist[4];
#pragma unroll
    for (int i = 0; i < 4; i++) {
        int n = base + i*256 + tid;
        px[i] = xb[n]; py[i] = xb[Np + n]; pz[i] = xb[2*Np + n];
        dist[i] = 1e10f;
    }

    __shared__ unsigned long long s_w[8];
    __shared__ float s_cx, s_cy, s_cz;
    __shared__ int   s_ci;

    int   cur = 0;
    float cx = xb[0], cy = xb[Np], cz = xb[2*Np];
    volatile unsigned int* cnt = &g_cnt[b];

    for (int s = 0; s < Sq; s++) {
        if (j == 0 && tid == 0) {
            g_fps_idx[b*Sq + s] = cur;
            out[b*3*Sq + s]          = cx;
            out[b*3*Sq + Sq + s]     = cy;
            out[b*3*Sq + 2*Sq + s]   = cz;
        }
        if (s == Sq - 1) break;

        // update distances + local packed argmax (max dist, min index on ties)
        unsigned long long best = 0ull;
#pragma unroll
        for (int i = 0; i < 4; i++) {
            float dx = px[i] - cx, dy = py[i] - cy, dz = pz[i] - cz;
            float d  = dx*dx + dy*dy + dz*dz;
            float nd = fminf(dist[i], d);
            dist[i] = nd;
            int n = base + i*256 + tid;
            unsigned long long pk =
                ((unsigned long long)__float_as_uint(nd) << 32) |
                (unsigned int)(0xFFFFFFFFu - (unsigned)n);
            best = pk_max(best, pk);
        }
#pragma unroll
        for (int o = 16; o; o >>= 1)
            best = pk_max(best, __shfl_down_sync(0xffffffffu, best, o));

        int wid = tid >> 5, lane = tid & 31;
        if (lane == 0) s_w[wid] = best;
        __syncthreads();

        if (wid == 0) {
            best = (lane < 8) ? s_w[lane] : 0ull;
#pragma unroll
            for (int o = 4; o; o >>= 1)
                best = pk_max(best, __shfl_down_sync(0xffffffffu, best, o));

            int par = s & 1;
            if (lane == 0) {
                ((volatile unsigned long long*)&g_part[b][par][0])[j] = best;
                __threadfence();
                atomicAdd(&g_cnt[b], 1u);
            }
            unsigned int target = 16u * (unsigned)(s + 1);
            while (*cnt < target) { }

            unsigned long long pk =
                (lane < 16) ? ((volatile unsigned long long*)&g_part[b][par][0])[lane] : 0ull;
#pragma unroll
            for (int o = 8; o; o >>= 1)
                pk = pk_max(pk, __shfl_down_sync(0xffffffffu, pk, o));
            if (lane == 0) {
                int w = (int)(0xFFFFFFFFu - (unsigned int)(pk & 0xFFFFFFFFull));
                s_ci = w;
                s_cx = xb[w]; s_cy = xb[Np + w]; s_cz = xb[2*Np + w];
            }
        }
        __syncthreads();
        cur = s_ci; cx = s_cx; cy = s_cy; cz = s_cz;
    }
}

// ---------------- kNN: branchless register top-K insertion ----------------
__global__ void __launch_bounds__(128) k_knn(const float* __restrict__ xyz) {
    int b = blockIdx.y;
    int s = blockIdx.x * 128 + threadIdx.x;
    const float* xb = xyz + b*3*Np;
    int qn = g_fps_idx[b*Sq + s];
    float qx = xb[qn], qy = xb[Np + qn], qz = xb[2*Np + qn];
    float q2 = qx*qx + qy*qy + qz*qz;

    float bd[Kq]; int bi[Kq];
#pragma unroll
    for (int k = 0; k < Kq; k++) { bd[k] = 3.0e38f; bi[k] = 0; }

    __shared__ float4 sp[512];
    for (int n0 = 0; n0 < Np; n0 += 512) {
        __syncthreads();
        for (int t = threadIdx.x; t < 512; t += 128) {
            float x = xb[n0 + t], y = xb[Np + n0 + t], z = xb[2*Np + n0 + t];
            sp[t] = make_float4(x, y, z, x*x + y*y + z*z);
        }
        __syncthreads();
#pragma unroll 2
        for (int t = 0; t < 512; t++) {
            float4 p = sp[t];
            float d = (q2 + p.w) - 2.0f * (qx*p.x + qy*p.y + qz*p.z);
            if (d < bd[Kq-1]) {
                int ii = n0 + t;
#pragma unroll
                for (int k = Kq - 1; k > 0; k--) {
                    bool ck   = d < bd[k];
                    bool ckm1 = d < bd[k-1];
                    float nv = ckm1 ? bd[k-1] : d;
                    int   ni = ckm1 ? bi[k-1] : ii;
                    bd[k] = ck ? nv : bd[k];
                    bi[k] = ck ? ni : bi[k];
                }
                bool c0 = d < bd[0];
                bd[0] = c0 ? d : bd[0];
                bi[0] = c0 ? ii : bi[0];
            }
        }
    }
    int o = (b*Sq + s) * Kq;
#pragma unroll
    for (int k = 0; k < Kq; k++) g_knn_idx[o + k] = bi[k];
}

// ---------------- transpose points (B,C,N) -> (B,N,C) ----------------
__global__ void k_transpose(const float* __restrict__ pts) {
    __shared__ float tile[32][33];
    int b  = blockIdx.z;
    int n0 = blockIdx.x * 32, c0 = blockIdx.y * 32;
    int x = threadIdx.x, y = threadIdx.y;
    for (int r = y; r < 32; r += 8)
        tile[r][x] = pts[(long)b*CIN*Np + (c0 + r)*Np + n0 + x];
    __syncthreads();
    for (int r = y; r < 32; r += 8)
        g_pointsT[((long)b*Np + (n0 + r)) * CIN + c0 + x] = tile[x][r];
}

// ---------------- gather + concat -> feats [p][67] ----------------
__global__ void k_gather(const float* __restrict__ xyz) {
    long t = (long)blockIdx.x * blockDim.x + threadIdx.x;
    if (t >= (long)PTOT * C0) return;
    int p = (int)(t / C0);
    int i = (int)(t - (long)p * C0);
    int b = p >> 16;
    int s = (p >> 5) & (Sq - 1);
    int n = g_knn_idx[p];
    float v;
    if (i < 3) {
        const float* xb = xyz + b*3*Np;
        int q = g_fps_idx[b*Sq + s];
        v = xb[i*Np + n] - xb[i*Np + q];
    } else {
        v = g_pointsT[((long)b*Np + n) * CIN + (i - 3)];
    }
    g_feats[t] = v;
}

// ---------------- conv GEMM + fused BN-of-prev + fused stats (+max/min for L2) ----
template<int LAYER>
__global__ void __launch_bounds__(256) k_conv(const float* __restrict__ W) {
    constexpr int CI = (LAYER == 0) ? 67 : 64;
    constexpr int CO = (LAYER == 2) ? 128 : 64;
    constexpr bool BN = (LAYER != 0);
    constexpr int TN = CO / 16;
    const float* A = (LAYER == 0) ? g_feats : ((LAYER == 1) ? g_x0 : g_x1);
    float*       O = (LAYER == 0) ? g_x0 : g_x1;

    __shared__ __align__(16) float sA[16][68];
    __shared__ __align__(16) float sBt[16][CO + 4];
    __shared__ float sS[64], sH[64];
    __shared__ float sSum[16][CO], sSq[16][CO];
    __shared__ float sMx[(LAYER == 2) ? 16 : 1][(LAYER == 2) ? CO : 1];
    __shared__ float sMn[(LAYER == 2) ? 16 : 1][(LAYER == 2) ? CO : 1];

    int tid = threadIdx.x;
    int m0  = blockIdx.x * 64;
    int tx = tid & 15, ty = tid >> 4;

    if (BN && tid < CI) { sS[tid] = g_scale[tid]; sH[tid] = g_shift[tid]; }

    float acc[4][TN];
#pragma unroll
    for (int i = 0; i < 4; i++)
#pragma unroll
        for (int jj = 0; jj < TN; jj++) acc[i][jj] = 0.f;

    const int KCH = (CI + 15) / 16;
    for (int kc = 0; kc < KCH; kc++) {
        int k0 = kc * 16;
        __syncthreads();
#pragma unroll
        for (int r = 0; r < 4; r++) {
            int e = tid + 256 * r;
            int m = e >> 4, kk = e & 15;
            int col = k0 + kk;
            float v = 0.f;
            if (col < CI) {
                v = A[(m0 + m) * CI + col];
                if (BN) v = fmaxf(v * sS[col] + sH[col], 0.f);
            }
            sA[kk][m] = v;
        }
#pragma unroll
        for (int r = 0; r < (CO * 16) / 256; r++) {
            int e = tid + 256 * r;
            int co = e >> 4, kk = e & 15;
            int col = k0 + kk;
            sBt[kk][co] = (col < CI) ? W[co * CI + col] : 0.f;
        }
        __syncthreads();
#pragma unroll
        for (int kk = 0; kk < 16; kk++) {
            float4 a4 = *(const float4*)&sA[kk][ty * 4];
            float a[4] = {a4.x, a4.y, a4.z, a4.w};
            float bb[TN];
#pragma unroll
            for (int q = 0; q < TN; q += 4) {
                float4 b4 = *(const float4*)&sBt[kk][tx * TN + q];
                bb[q] = b4.x; bb[q+1] = b4.y; bb[q+2] = b4.z; bb[q+3] = b4.w;
            }
#pragma unroll
            for (int i = 0; i < 4; i++)
#pragma unroll
                for (int jj = 0; jj < TN; jj++)
                    acc[i][jj] += a[i] * bb[jj];
        }
    }

    if (LAYER < 2) {
#pragma unroll
        for (int i = 0; i < 4; i++) {
            int row = m0 + ty * 4 + i;
#pragma unroll
            for (int jj = 0; jj < TN; jj += 4) {
                float4 v = make_float4(acc[i][jj], acc[i][jj+1], acc[i][jj+2], acc[i][jj+3]);
                *(float4*)&O[row * CO + tx * TN + jj] = v;
            }
        }
    }

#pragma unroll
    for (int jj = 0; jj < TN; jj++) {
        float cs = 0.f, cq = 0.f;
        float mx = -3.0e38f, mn = 3.0e38f;
#pragma unroll
        for (int i = 0; i < 4; i++) {
            float v = acc[i][jj];
            cs += v; cq = fmaf(v, v, cq);
            mx = fmaxf(mx, v); mn = fminf(mn, v);
        }
        int col = tx * TN + jj;
        sSum[ty][col] = cs;
        sSq[ty][col]  = cq;
        if (LAYER == 2) { sMx[ty][col] = mx; sMn[ty][col] = mn; }
    }
    __syncthreads();
    if (tid < CO) {
        float s = 0.f, q = 0.f;
#pragma unroll
        for (int r = 0; r < 16; r++) { s += sSum[r][tid]; q += sSq[r][tid]; }
        atomicAdd(&g_stats[tid], s);
        atomicAdd(&g_stats[128 + tid], q);
    }
    if (LAYER == 2) {
        int h = tid >> 7, c = tid & 127;
        float mx = -3.0e38f, mn = 3.0e38f;
#pragma unroll
        for (int r = 0; r < 8; r++) {
            mx = fmaxf(mx, sMx[h*8 + r][c]);
            mn = fminf(mn, sMn[h*8 + r][c]);
        }
        int bs = (m0 >> 5) + h;
        g_mx[(long)bs * C3 + c] = mx;
        g_mn[(long)bs * C3 + c] = mn;
    }
}

// ---------------- BN finalize ----------------
__global__ void k_bnfin(const float* __restrict__ g, const float* __restrict__ bb, int CO) {
    int c = threadIdx.x;
    if (c < CO) {
        const float inv = 1.0f / (float)PTOT;
        float mean = g_stats[c] * inv;
        float var  = fmaxf(g_stats[128 + c] * inv - mean * mean, 0.f);
        float sc   = g[c] / sqrtf(var + EPSV);
        g_scale[c] = sc;
        g_shift[c] = bb[c] - mean * sc;
    }
}

// ---------------- final: BN2+ReLU+maxpool from (mx,mn), transposed store ------
__global__ void __launch_bounds__(256) k_final(float* __restrict__ out) {
    __shared__ float sOut[128][33];
    int b  = blockIdx.y;
    int s0 = blockIdx.x * 32;
    int t  = threadIdx.x;
#pragma unroll
    for (int i = 0; i < 16; i++) {
        int idx = i * 256 + t;
        int c = idx & 127, r = idx >> 7;
        long bs = (long)(b * Sq + s0 + r);
        float sc = g_scale[c], sh = g_shift[c];
        float v = (sc >= 0.f) ? g_mx[bs * C3 + c] : g_mn[bs * C3 + c];
        sOut[c][r] = fmaxf(v * sc + sh, 0.f);
    }
    __syncthreads();
#pragma unroll
    for (int i = 0; i < 16; i++) {
        int idx = i * 256 + t;
        int c = idx >> 5, r = idx & 31;
        out[Bq*3*Sq + b*C3*Sq + c*Sq + s0 + r] = sOut[c][r];
    }
}

// ---------------- launch ----------------
extern "C" void kernel_launch(void* const* d_in, const int* in_sizes, int n_in,
                              void* d_out, int out_size) {
    const float* xyz    = (const float*)d_in[0];
    const float* points = (const float*)d_in[1];
    const float* W0 = (const float*)d_in[2];
    const float* g0 = (const float*)d_in[3];
    const float* b0 = (const float*)d_in[4];
    const float* W1 = (const float*)d_in[5];
    const float* g1 = (const float*)d_in[6];
    const float* b1 = (const float*)d_in[7];
    const float* W2 = (const float*)d_in[8];
    const float* g2 = (const float*)d_in[9];
    const float* b2 = (const float*)d_in[10];
    float* out = (float*)d_out;

    k_zero<<<1, 256>>>();
    k_fps<<<dim3(16, Bq), 256>>>(xyz, out);
    k_knn<<<dim3(Sq/128, Bq), 128>>>(xyz);
    k_transpose<<<dim3(Np/32, CIN/32, Bq), dim3(32, 8)>>>(points);
    {
        long tot = (long)PTOT * C0;
        k_gather<<<(unsigned)((tot + 255) / 256), 256>>>(xyz);
    }
    k_conv<0><<<PTOT/64, 256>>>(W0);
    k_bnfin<<<1, 128>>>(g0, b0, 64);
    k_zstats<<<1, 256>>>();

    k_conv<1><<<PTOT/64, 256>>>(W1);
    k_bnfin<<<1, 128>>>(g1, b1, 64);
    k_zstats<<<1, 256>>>();

    k_conv<2><<<PTOT/64, 256>>>(W2);
    k_bnfin<<<1, 128>>>(g2, b2, 128);

    k_final<<<dim3(Sq/32, Bq), 256>>>(out);
}